// round 2
// baseline (speedup 1.0000x reference)
#include <cuda_runtime.h>

#define N_IMG 8
#define C_IN  256
#define C_OUT 256
#define H_DIM 64
#define W_DIM 64
#define HW    4096
#define GROUPS 32
#define EPS_GN 1e-5f
#define CK    (C_IN * 9)   // 2304

// Scratch (static device globals; no runtime allocation)
__device__ float4 g_T[N_IMG * HW];        // per-pixel 2x2 transform (t00,t01,t10,t11)
__device__ float  g_wT[CK * C_OUT];       // dcn weights transposed: [c*9+k][o]
__device__ float2 g_stats[N_IMG * GROUPS];// (mu, rsigma) per (n, group)

// ---------------------------------------------------------------------------
// Kernel 0: transpose w_dcn [o][c][k] -> g_wT [c*9+k][o] for coalesced reads
// ---------------------------------------------------------------------------
__global__ void k_transpose_w(const float* __restrict__ w) {
    int i = blockIdx.x * 256 + threadIdx.x;          // i = o*CK + ck
    if (i >= C_OUT * CK) return;
    int o  = i / CK;
    int ck = i - o * CK;
    g_wT[ck * C_OUT + o] = w[i];
}

// ---------------------------------------------------------------------------
// Kernel 1: tm = conv3x3(x, w_tm) + b_tm  -> store T (4 floats) per pixel
// ---------------------------------------------------------------------------
__global__ void __launch_bounds__(256) k_offsets(const float* __restrict__ x,
                                                 const float* __restrict__ w_tm,
                                                 const float* __restrict__ b_tm) {
    __shared__ float4 ws[CK];                        // [c*9+k] -> (w_j0..w_j3), 36 KB
    int tid = threadIdx.x;
    for (int i = tid; i < CK; i += 256) {
        ws[i] = make_float4(w_tm[i], w_tm[CK + i], w_tm[2 * CK + i], w_tm[3 * CK + i]);
    }
    __syncthreads();

    int P  = blockIdx.x * 256 + tid;                 // flat pixel
    int n  = P >> 12;
    int y  = (P >> 6) & 63;
    int xc = P & 63;

    float t0 = __ldg(b_tm + 0), t1 = __ldg(b_tm + 1);
    float t2 = __ldg(b_tm + 2), t3 = __ldg(b_tm + 3);

    int  doff[9];
    bool vld[9];
#pragma unroll
    for (int k = 0; k < 9; k++) {
        int dy = k / 3 - 1, dx = k % 3 - 1;
        int yy = y + dy, xx = xc + dx;
        vld[k]  = (yy >= 0) && (yy < H_DIM) && (xx >= 0) && (xx < W_DIM);
        doff[k] = dy * W_DIM + dx;
    }

    const float* xp = x + ((size_t)n * C_IN) * HW + y * W_DIM + xc;
    for (int c = 0; c < C_IN; c++) {
        const float* xpc = xp + c * HW;
#pragma unroll
        for (int k = 0; k < 9; k++) {
            float v = vld[k] ? __ldg(xpc + doff[k]) : 0.0f;
            float4 w4 = ws[c * 9 + k];
            t0 = fmaf(v, w4.x, t0);
            t1 = fmaf(v, w4.y, t1);
            t2 = fmaf(v, w4.z, t2);
            t3 = fmaf(v, w4.w, t3);
        }
    }
    g_T[P] = make_float4(t0, t1, t2, t3);
}

// ---------------------------------------------------------------------------
// Kernel 2: deformable conv. Block = one image row (64 pixels), thread = o.
// Implicit-im2col GEMM with double-buffered smem val tiles.
// ---------------------------------------------------------------------------
__global__ void __launch_bounds__(256, 2) k_deform(const float* __restrict__ x,
                                                   float* __restrict__ out) {
    __shared__ int4   s_idx[576];          // per (p,k): 4 clamped gather indices
    __shared__ float4 s_w[576];            // per (p,k): 4 bilinear weights (0 if OOB)
    __shared__ float  s_val[2][64 * 12];   // double-buffered val[p][k], k padded to 12

    int tid = threadIdx.x;
    int R = blockIdx.x;                    // row id = n*64 + y
    int n = R >> 6;
    int y = R & 63;

    // --- precompute bilinear params for all 64 pixels x 9 taps ---
    for (int v = tid; v < 576; v += 256) {
        int p = v / 9, k = v - p * 9;
        float4 T = g_T[R * 64 + p];
        float dy = (float)(k / 3 - 1), dx = (float)(k % 3 - 1);
        float py = (float)y + T.x * dy + T.y * dx;
        float px = (float)p + T.z * dy + T.w * dx;
        float y0f = floorf(py), x0f = floorf(px);
        float wy = py - y0f, wx = px - x0f;
        int iy0 = (int)y0f, ix0 = (int)x0f;
        int iy1 = iy0 + 1,  ix1 = ix0 + 1;
        bool vy0 = (iy0 >= 0) && (iy0 <= H_DIM - 1);
        bool vy1 = (iy1 >= 0) && (iy1 <= H_DIM - 1);
        bool vx0 = (ix0 >= 0) && (ix0 <= W_DIM - 1);
        bool vx1 = (ix1 >= 0) && (ix1 <= W_DIM - 1);
        int cy0 = min(H_DIM - 1, max(0, iy0)), cy1 = min(H_DIM - 1, max(0, iy1));
        int cx0 = min(W_DIM - 1, max(0, ix0)), cx1 = min(W_DIM - 1, max(0, ix1));
        float w00 = (vy0 && vx0) ? (1.f - wy) * (1.f - wx) : 0.f;
        float w01 = (vy0 && vx1) ? (1.f - wy) * wx         : 0.f;
        float w10 = (vy1 && vx0) ? wy * (1.f - wx)         : 0.f;
        float w11 = (vy1 && vx1) ? wy * wx                 : 0.f;
        s_idx[v] = make_int4(cy0 * W_DIM + cx0, cy0 * W_DIM + cx1,
                             cy1 * W_DIM + cx0, cy1 * W_DIM + cx1);
        s_w[v]   = make_float4(w00, w01, w10, w11);
    }
    // zero pad columns (k=9..11) of both val buffers
    for (int i = tid; i < 2 * 64 * 12; i += 256) ((float*)s_val)[i] = 0.f;
    __syncthreads();

    // builder assignments: each thread owns up to 3 (p,k) entries
    int v0 = tid, v1 = tid + 256, v2 = tid + 512;          // v2 valid iff tid < 64
    int o0 = (v0 / 9) * 12 + v0 % 9;
    int o1 = (v1 / 9) * 12 + v1 % 9;
    int o2 = (v2 < 576) ? (v2 / 9) * 12 + v2 % 9 : 0;

    const float* xb = x + (size_t)n * C_IN * HW;
    float acc[64];
#pragma unroll
    for (int p = 0; p < 64; p++) acc[p] = 0.f;

    // build c = 0 into buffer 0
    {
        const float* xp = xb;
        int4 id = s_idx[v0]; float4 wt = s_w[v0];
        s_val[0][o0] = wt.x * __ldg(xp + id.x) + wt.y * __ldg(xp + id.y)
                     + wt.z * __ldg(xp + id.z) + wt.w * __ldg(xp + id.w);
        id = s_idx[v1]; wt = s_w[v1];
        s_val[0][o1] = wt.x * __ldg(xp + id.x) + wt.y * __ldg(xp + id.y)
                     + wt.z * __ldg(xp + id.z) + wt.w * __ldg(xp + id.w);
        if (v2 < 576) {
            id = s_idx[v2]; wt = s_w[v2];
            s_val[0][o2] = wt.x * __ldg(xp + id.x) + wt.y * __ldg(xp + id.y)
                         + wt.z * __ldg(xp + id.z) + wt.w * __ldg(xp + id.w);
        }
    }
    __syncthreads();

    const float* wb = g_wT + tid;                     // o = tid, coalesced
    for (int c = 0; c < C_IN; c++) {
        int cur = c & 1;
        if (c + 1 < C_IN) {                            // prefetch/build next channel
            const float* xp = xb + (c + 1) * HW;
            int nb = cur ^ 1;
            int4 id = s_idx[v0]; float4 wt = s_w[v0];
            s_val[nb][o0] = wt.x * __ldg(xp + id.x) + wt.y * __ldg(xp + id.y)
                          + wt.z * __ldg(xp + id.z) + wt.w * __ldg(xp + id.w);
            id = s_idx[v1]; wt = s_w[v1];
            s_val[nb][o1] = wt.x * __ldg(xp + id.x) + wt.y * __ldg(xp + id.y)
                          + wt.z * __ldg(xp + id.z) + wt.w * __ldg(xp + id.w);
            if (v2 < 576) {
                id = s_idx[v2]; wt = s_w[v2];
                s_val[nb][o2] = wt.x * __ldg(xp + id.x) + wt.y * __ldg(xp + id.y)
                              + wt.z * __ldg(xp + id.z) + wt.w * __ldg(xp + id.w);
            }
        }
        const float* wp = wb + c * 9 * C_OUT;
        float w0 = __ldg(wp);            float w1 = __ldg(wp + 1 * C_OUT);
        float w2 = __ldg(wp + 2 * C_OUT); float w3 = __ldg(wp + 3 * C_OUT);
        float w4 = __ldg(wp + 4 * C_OUT); float w5 = __ldg(wp + 5 * C_OUT);
        float w6 = __ldg(wp + 6 * C_OUT); float w7 = __ldg(wp + 7 * C_OUT);
        float w8 = __ldg(wp + 8 * C_OUT);

        const float4* vb = (const float4*)(s_val[cur]);
#pragma unroll
        for (int p = 0; p < 64; p++) {
            float4 a = vb[3 * p + 0];
            float4 b = vb[3 * p + 1];
            float4 d = vb[3 * p + 2];
            float s = fmaf(a.x, w0, fmaf(a.y, w1, fmaf(a.z, w2, fmaf(a.w, w3,
                      fmaf(b.x, w4, fmaf(b.y, w5, fmaf(b.z, w6, fmaf(b.w, w7,
                      d.x * w8))))))));
            acc[p] += s;
        }
        __syncthreads();
    }

    // epilogue: thread tid (=o) owns a contiguous 64-float output row
    float4* op = (float4*)(out + ((size_t)(n * C_OUT + tid)) * HW + y * W_DIM);
#pragma unroll
    for (int i = 0; i < 16; i++)
        op[i] = make_float4(acc[4 * i], acc[4 * i + 1], acc[4 * i + 2], acc[4 * i + 3]);
}

// ---------------------------------------------------------------------------
// Kernel 3: GroupNorm statistics. One block per (n, group): 8 ch x 4096 px.
// ---------------------------------------------------------------------------
__global__ void __launch_bounds__(256) k_gn_stats(const float* __restrict__ out) {
    int gidx = blockIdx.x;                                // n*32 + g
    const float4* p = (const float4*)(out + (size_t)gidx * 8 * HW);
    int tid = threadIdx.x;
    float s = 0.f, s2 = 0.f;
    for (int i = tid; i < 8 * HW / 4; i += 256) {
        float4 v = p[i];
        s  += (v.x + v.y) + (v.z + v.w);
        s2  = fmaf(v.x, v.x, fmaf(v.y, v.y, fmaf(v.z, v.z, fmaf(v.w, v.w, s2))));
    }
    __shared__ float sh[2][8];
#pragma unroll
    for (int off = 16; off; off >>= 1) {
        s  += __shfl_down_sync(0xffffffffu, s, off);
        s2 += __shfl_down_sync(0xffffffffu, s2, off);
    }
    int warp = tid >> 5;
    if ((tid & 31) == 0) { sh[0][warp] = s; sh[1][warp] = s2; }
    __syncthreads();
    if (tid == 0) {
        float a = 0.f, b = 0.f;
#pragma unroll
        for (int i = 0; i < 8; i++) { a += sh[0][i]; b += sh[1][i]; }
        const float inv = 1.f / (8.f * HW);
        float mu  = a * inv;
        float var = b * inv - mu * mu;
        g_stats[gidx] = make_float2(mu, rsqrtf(var + EPS_GN));
    }
}

// ---------------------------------------------------------------------------
// Kernel 4: normalize + affine + ReLU, in place on d_out.
// ---------------------------------------------------------------------------
__global__ void __launch_bounds__(256) k_gn_norm(float* __restrict__ out,
                                                 const float* __restrict__ gamma,
                                                 const float* __restrict__ beta) {
    int f = blockIdx.x * 256 + threadIdx.x;               // float4 index
    int plane = f >> 10;                                  // 1024 float4 per channel plane
    int c = plane & 255;
    float2 st = g_stats[plane >> 3];                      // n*32 + c/8
    float ga = __ldg(gamma + c) * st.y;
    float be = __ldg(beta + c) - st.x * ga;
    float4* p = (float4*)out + f;
    float4 v = *p;
    v.x = fmaxf(fmaf(v.x, ga, be), 0.f);
    v.y = fmaxf(fmaf(v.y, ga, be), 0.f);
    v.z = fmaxf(fmaf(v.z, ga, be), 0.f);
    v.w = fmaxf(fmaf(v.w, ga, be), 0.f);
    *p = v;
}

// ---------------------------------------------------------------------------
extern "C" void kernel_launch(void* const* d_in, const int* in_sizes, int n_in,
                              void* d_out, int out_size) {
    (void)in_sizes; (void)n_in; (void)out_size;
    const float* x     = (const float*)d_in[0];
    const float* w_tm  = (const float*)d_in[1];
    const float* b_tm  = (const float*)d_in[2];
    const float* w_dcn = (const float*)d_in[3];
    const float* gamma = (const float*)d_in[4];
    const float* beta  = (const float*)d_in[5];
    float* out = (float*)d_out;

    k_transpose_w<<<(C_OUT * CK + 255) / 256, 256>>>(w_dcn);
    k_offsets<<<N_IMG * HW / 256, 256>>>(x, w_tm, b_tm);
    k_deform<<<N_IMG * H_DIM, 256>>>(x, out);
    k_gn_stats<<<N_IMG * GROUPS, 256>>>(out);
    k_gn_norm<<<(N_IMG * C_OUT * HW / 4) / 256, 256>>>(out, gamma, beta);
}

// round 3
// speedup vs baseline: 1.2658x; 1.2658x over previous
#include <cuda_runtime.h>

#define N_IMG 8
#define C_IN  256
#define C_OUT 256
#define H_DIM 64
#define W_DIM 64
#define HW    4096
#define GROUPS 32
#define EPS_GN 1e-5f
#define CK    (C_IN * 9)   // 2304

#define ROWP  68           // padded row stride (floats) for k-major val tile
#define CHF   (9 * ROWP)   // floats per channel tile = 612

// Scratch (static device globals; no runtime allocation)
__device__ float4 g_T[N_IMG * HW];        // per-pixel 2x2 transform (t00,t01,t10,t11)
__device__ float  g_wT[CK * C_OUT];       // dcn weights transposed: [c*9+k][o]
__device__ float2 g_stats[N_IMG * GROUPS];// (mu, rsigma) per (n, group)

// ---------------------------------------------------------------------------
// Kernel 0: transpose w_dcn [o][c][k] -> g_wT [c*9+k][o] for coalesced reads
// ---------------------------------------------------------------------------
__global__ void k_transpose_w(const float* __restrict__ w) {
    int i = blockIdx.x * 256 + threadIdx.x;          // i = o*CK + ck
    if (i >= C_OUT * CK) return;
    int o  = i / CK;
    int ck = i - o * CK;
    g_wT[ck * C_OUT + o] = w[i];
}

// ---------------------------------------------------------------------------
// Kernel 1: tm = conv3x3(x, w_tm) + b_tm  -> store T (4 floats) per pixel
// ---------------------------------------------------------------------------
__global__ void __launch_bounds__(256) k_offsets(const float* __restrict__ x,
                                                 const float* __restrict__ w_tm,
                                                 const float* __restrict__ b_tm) {
    __shared__ float4 ws[CK];                        // [c*9+k] -> (w_j0..w_j3), 36 KB
    int tid = threadIdx.x;
    for (int i = tid; i < CK; i += 256) {
        ws[i] = make_float4(w_tm[i], w_tm[CK + i], w_tm[2 * CK + i], w_tm[3 * CK + i]);
    }
    __syncthreads();

    int P  = blockIdx.x * 256 + tid;                 // flat pixel
    int n  = P >> 12;
    int y  = (P >> 6) & 63;
    int xc = P & 63;

    float t0 = __ldg(b_tm + 0), t1 = __ldg(b_tm + 1);
    float t2 = __ldg(b_tm + 2), t3 = __ldg(b_tm + 3);

    int  doff[9];
    bool vld[9];
#pragma unroll
    for (int k = 0; k < 9; k++) {
        int dy = k / 3 - 1, dx = k % 3 - 1;
        int yy = y + dy, xx = xc + dx;
        vld[k]  = (yy >= 0) && (yy < H_DIM) && (xx >= 0) && (xx < W_DIM);
        doff[k] = dy * W_DIM + dx;
    }

    const float* xp = x + ((size_t)n * C_IN) * HW + y * W_DIM + xc;
    for (int c = 0; c < C_IN; c++) {
        const float* xpc = xp + c * HW;
#pragma unroll
        for (int k = 0; k < 9; k++) {
            float v = vld[k] ? __ldg(xpc + doff[k]) : 0.0f;
            float4 w4 = ws[c * 9 + k];
            t0 = fmaf(v, w4.x, t0);
            t1 = fmaf(v, w4.y, t1);
            t2 = fmaf(v, w4.z, t2);
            t3 = fmaf(v, w4.w, t3);
        }
    }
    g_T[P] = make_float4(t0, t1, t2, t3);
}

// ---------------------------------------------------------------------------
// Kernel 2: deformable conv. Block = one image row (64 pixels), thread = o.
// Implicit-im2col GEMM. Packed fp32x2 FMA (fma.rn.f32x2), k-major smem val
// tiles (val[k][p], pixel pairs contiguous), 2 channels per buffer.
// ---------------------------------------------------------------------------
__global__ void __launch_bounds__(256, 2) k_deform(const float* __restrict__ x,
                                                   float* __restrict__ out) {
    __shared__ int4   s_idx[576];          // per (p,k): 4 clamped gather indices
    __shared__ float4 s_w[576];            // per (p,k): 4 bilinear weights (0 if OOB)
    __shared__ float  s_val[2][2 * CHF];   // double-buffered, 2 channels per buffer

    int tid = threadIdx.x;
    int R = blockIdx.x;                    // row id = n*64 + y
    int n = R >> 6;
    int y = R & 63;

    // --- precompute bilinear params for all 64 pixels x 9 taps ---
    for (int v = tid; v < 576; v += 256) {
        int p = v / 9, k = v - p * 9;
        float4 T = g_T[R * 64 + p];
        float dy = (float)(k / 3 - 1), dx = (float)(k % 3 - 1);
        float py = (float)y + T.x * dy + T.y * dx;
        float px = (float)p + T.z * dy + T.w * dx;
        float y0f = floorf(py), x0f = floorf(px);
        float wy = py - y0f, wx = px - x0f;
        int iy0 = (int)y0f, ix0 = (int)x0f;
        int iy1 = iy0 + 1,  ix1 = ix0 + 1;
        bool vy0 = (iy0 >= 0) && (iy0 <= H_DIM - 1);
        bool vy1 = (iy1 >= 0) && (iy1 <= H_DIM - 1);
        bool vx0 = (ix0 >= 0) && (ix0 <= W_DIM - 1);
        bool vx1 = (ix1 >= 0) && (ix1 <= W_DIM - 1);
        int cy0 = min(H_DIM - 1, max(0, iy0)), cy1 = min(H_DIM - 1, max(0, iy1));
        int cx0 = min(W_DIM - 1, max(0, ix0)), cx1 = min(W_DIM - 1, max(0, ix1));
        float w00 = (vy0 && vx0) ? (1.f - wy) * (1.f - wx) : 0.f;
        float w01 = (vy0 && vx1) ? (1.f - wy) * wx         : 0.f;
        float w10 = (vy1 && vx0) ? wy * (1.f - wx)         : 0.f;
        float w11 = (vy1 && vx1) ? wy * wx                 : 0.f;
        s_idx[v] = make_int4(cy0 * W_DIM + cx0, cy0 * W_DIM + cx1,
                             cy1 * W_DIM + cx0, cy1 * W_DIM + cx1);
        s_w[v]   = make_float4(w00, w01, w10, w11);
    }
    __syncthreads();

    // builder assignments: each thread owns up to 3 (p,k) entries.
    // k-major destination: offset = k*ROWP + p
    int v0 = tid, v1 = tid + 256, v2 = tid + 512;          // v2 valid iff tid < 64
    int o0 = (v0 % 9) * ROWP + v0 / 9;
    int o1 = (v1 % 9) * ROWP + v1 / 9;
    int o2 = (v2 < 576) ? (v2 % 9) * ROWP + v2 / 9 : 0;
    int4   id0 = s_idx[v0], id1 = s_idx[v1], id2 = s_idx[(v2 < 576) ? v2 : 0];
    float4 wt0 = s_w[v0],   wt1 = s_w[v1],   wt2 = s_w[(v2 < 576) ? v2 : 0];

    const float* xb = x + (size_t)n * C_IN * HW;
    unsigned long long acc2[32];           // 32 packed fp32x2 = 64 pixel accumulators
#pragma unroll
    for (int i = 0; i < 32; i++) acc2[i] = 0ULL;

    // build channels 0,1 into buffer 0
#pragma unroll
    for (int u = 0; u < 2; u++) {
        const float* xp = xb + u * HW;
        float* dst = s_val[0] + u * CHF;
        dst[o0] = wt0.x * __ldg(xp + id0.x) + wt0.y * __ldg(xp + id0.y)
                + wt0.z * __ldg(xp + id0.z) + wt0.w * __ldg(xp + id0.w);
        dst[o1] = wt1.x * __ldg(xp + id1.x) + wt1.y * __ldg(xp + id1.y)
                + wt1.z * __ldg(xp + id1.z) + wt1.w * __ldg(xp + id1.w);
        if (v2 < 576)
            dst[o2] = wt2.x * __ldg(xp + id2.x) + wt2.y * __ldg(xp + id2.y)
                    + wt2.z * __ldg(xp + id2.z) + wt2.w * __ldg(xp + id2.w);
    }
    __syncthreads();

    const float* wb = g_wT + tid;                     // o = tid, coalesced
    for (int cc = 0; cc < C_IN / 2; cc++) {
        int cur = cc & 1;
        if (cc + 1 < C_IN / 2) {                      // build next 2 channels
            int nb = cur ^ 1;
#pragma unroll
            for (int u = 0; u < 2; u++) {
                const float* xp = xb + (2 * (cc + 1) + u) * HW;
                float* dst = s_val[nb] + u * CHF;
                dst[o0] = wt0.x * __ldg(xp + id0.x) + wt0.y * __ldg(xp + id0.y)
                        + wt0.z * __ldg(xp + id0.z) + wt0.w * __ldg(xp + id0.w);
                dst[o1] = wt1.x * __ldg(xp + id1.x) + wt1.y * __ldg(xp + id1.y)
                        + wt1.z * __ldg(xp + id1.z) + wt1.w * __ldg(xp + id1.w);
                if (v2 < 576)
                    dst[o2] = wt2.x * __ldg(xp + id2.x) + wt2.y * __ldg(xp + id2.y)
                            + wt2.z * __ldg(xp + id2.z) + wt2.w * __ldg(xp + id2.w);
            }
        }
        // consume 2 channels from current buffer
#pragma unroll
        for (int u = 0; u < 2; u++) {
            const float* wp = wb + (size_t)(2 * cc + u) * 9 * C_OUT;
            unsigned long long W[9];
#pragma unroll
            for (int k = 0; k < 9; k++) {
                float w = __ldg(wp + k * C_OUT);
                asm("mov.b64 %0, {%1, %1};" : "=l"(W[k]) : "f"(w));
            }
            const float* vb = s_val[cur] + u * CHF;
#pragma unroll
            for (int k = 0; k < 9; k++) {
                const ulonglong2* row = (const ulonglong2*)(vb + k * ROWP);
#pragma unroll
                for (int i = 0; i < 16; i++) {
                    ulonglong2 v = row[i];   // 4 pixels, pre-packed as 2x f32x2
                    asm("fma.rn.f32x2 %0, %1, %2, %0;"
                        : "+l"(acc2[2 * i])     : "l"(v.x), "l"(W[k]));
                    asm("fma.rn.f32x2 %0, %1, %2, %0;"
                        : "+l"(acc2[2 * i + 1]) : "l"(v.y), "l"(W[k]));
                }
            }
        }
        __syncthreads();
    }

    // epilogue: thread tid (=o) owns a contiguous 64-float output row
    float4* op = (float4*)(out + ((size_t)(n * C_OUT + tid)) * HW + y * W_DIM);
#pragma unroll
    for (int i = 0; i < 16; i++) {
        union { unsigned long long u; float2 f; } a, b;
        a.u = acc2[2 * i];
        b.u = acc2[2 * i + 1];
        op[i] = make_float4(a.f.x, a.f.y, b.f.x, b.f.y);
    }
}

// ---------------------------------------------------------------------------
// Kernel 3: GroupNorm statistics. One block per (n, group): 8 ch x 4096 px.
// ---------------------------------------------------------------------------
__global__ void __launch_bounds__(256) k_gn_stats(const float* __restrict__ out) {
    int gidx = blockIdx.x;                                // n*32 + g
    const float4* p = (const float4*)(out + (size_t)gidx * 8 * HW);
    int tid = threadIdx.x;
    float s = 0.f, s2 = 0.f;
    for (int i = tid; i < 8 * HW / 4; i += 256) {
        float4 v = p[i];
        s  += (v.x + v.y) + (v.z + v.w);
        s2  = fmaf(v.x, v.x, fmaf(v.y, v.y, fmaf(v.z, v.z, fmaf(v.w, v.w, s2))));
    }
    __shared__ float sh[2][8];
#pragma unroll
    for (int off = 16; off; off >>= 1) {
        s  += __shfl_down_sync(0xffffffffu, s, off);
        s2 += __shfl_down_sync(0xffffffffu, s2, off);
    }
    int warp = tid >> 5;
    if ((tid & 31) == 0) { sh[0][warp] = s; sh[1][warp] = s2; }
    __syncthreads();
    if (tid == 0) {
        float a = 0.f, b = 0.f;
#pragma unroll
        for (int i = 0; i < 8; i++) { a += sh[0][i]; b += sh[1][i]; }
        const float inv = 1.f / (8.f * HW);
        float mu  = a * inv;
        float var = b * inv - mu * mu;
        g_stats[gidx] = make_float2(mu, rsqrtf(var + EPS_GN));
    }
}

// ---------------------------------------------------------------------------
// Kernel 4: normalize + affine + ReLU, in place on d_out.
// ---------------------------------------------------------------------------
__global__ void __launch_bounds__(256) k_gn_norm(float* __restrict__ out,
                                                 const float* __restrict__ gamma,
                                                 const float* __restrict__ beta) {
    int f = blockIdx.x * 256 + threadIdx.x;               // float4 index
    int plane = f >> 10;                                  // 1024 float4 per channel plane
    int c = plane & 255;
    float2 st = g_stats[plane >> 3];                      // n*32 + c/8
    float ga = __ldg(gamma + c) * st.y;
    float be = __ldg(beta + c) - st.x * ga;
    float4* p = (float4*)out + f;
    float4 v = *p;
    v.x = fmaxf(fmaf(v.x, ga, be), 0.f);
    v.y = fmaxf(fmaf(v.y, ga, be), 0.f);
    v.z = fmaxf(fmaf(v.z, ga, be), 0.f);
    v.w = fmaxf(fmaf(v.w, ga, be), 0.f);
    *p = v;
}

// ---------------------------------------------------------------------------
extern "C" void kernel_launch(void* const* d_in, const int* in_sizes, int n_in,
                              void* d_out, int out_size) {
    (void)in_sizes; (void)n_in; (void)out_size;
    const float* x     = (const float*)d_in[0];
    const float* w_tm  = (const float*)d_in[1];
    const float* b_tm  = (const float*)d_in[2];
    const float* w_dcn = (const float*)d_in[3];
    const float* gamma = (const float*)d_in[4];
    const float* beta  = (const float*)d_in[5];
    float* out = (float*)d_out;

    k_transpose_w<<<(C_OUT * CK + 255) / 256, 256>>>(w_dcn);
    k_offsets<<<N_IMG * HW / 256, 256>>>(x, w_tm, b_tm);
    k_deform<<<N_IMG * H_DIM, 256>>>(x, out);
    k_gn_stats<<<N_IMG * GROUPS, 256>>>(out);
    k_gn_norm<<<(N_IMG * C_OUT * HW / 4) / 256, 256>>>(out, gamma, beta);
}